// round 1
// baseline (speedup 1.0000x reference)
#include <cuda_runtime.h>
#include <cuda_bf16.h>

// S4D kernel: K[h,l] = 2*Re( sum_n Ct[h,n] * exp(dtA[h,n]*l) )
//   dt   = exp(log_dt[h])
//   A    = -exp(log_A_real) + i*A_imag
//   dtA  = A*dt,  z = exp(dtA)
//   Ct   = (C_real + i*C_imag) * (z - 1) / A
// Strategy: per-thread chunk of 16 l-values; geometric recurrence q *= z
// inside the chunk; chunk start computed directly (exp + double-reduced
// phase + __sincosf) to bound recurrence drift. 32 modes processed as 16
// packed pairs via f32x2 FMA-pipe instructions.

static constexpr int kH     = 1024;
static constexpr int kN2    = 32;
static constexpr int kL     = 4096;
static constexpr int kChunk = 16;
static constexpr int kTPB   = 256;           // kTPB * kChunk == kL
static constexpr int kPairs = kN2 / 2;

typedef unsigned long long u64;

__device__ __forceinline__ u64 pk2(float lo, float hi) {
    u64 r; asm("mov.b64 %0, {%1, %2};" : "=l"(r) : "f"(lo), "f"(hi)); return r;
}
__device__ __forceinline__ void upk2(u64 v, float& lo, float& hi) {
    asm("mov.b64 {%0, %1}, %2;" : "=f"(lo), "=f"(hi) : "l"(v));
}
__device__ __forceinline__ u64 fma2(u64 a, u64 b, u64 c) {
    u64 r; asm("fma.rn.f32x2 %0, %1, %2, %3;" : "=l"(r) : "l"(a), "l"(b), "l"(c)); return r;
}
__device__ __forceinline__ u64 mul2(u64 a, u64 b) {
    u64 r; asm("mul.rn.f32x2 %0, %1, %2;" : "=l"(r) : "l"(a), "l"(b)); return r;
}
__device__ __forceinline__ u64 add2(u64 a, u64 b) {
    u64 r; asm("add.rn.f32x2 %0, %1, %2;" : "=l"(r) : "l"(a), "l"(b)); return r;
}

// Compute q = Ct * z^{l0} for one mode (scalar). Phase reduced in double so
// |phase| up to ~4e4 stays accurate; magnitude via fast exp (underflow -> 0 ok).
__device__ __forceinline__ void chunk_start(float dre, float dimv, float ctr, float cti,
                                            float l0f, int l0, float& qr, float& qi) {
    const double INV2PI = 0.15915494309189535;
    const double TWOPI  = 6.283185307179586;
    float mag = __expf(dre * l0f);
    double ph = (double)dimv * (double)l0;
    double k  = rint(ph * INV2PI);
    float phr = (float)fma(-k, TWOPI, ph);
    float s, c;
    __sincosf(phr, &s, &c);
    float pr = mag * c, pi = mag * s;
    qr = ctr * pr - cti * pi;
    qi = ctr * pi + cti * pr;
}

__global__ __launch_bounds__(kTPB) void s4d_kernel(
    const float* __restrict__ log_dt,
    const float* __restrict__ C_real,
    const float* __restrict__ C_imag,
    const float* __restrict__ log_A_real,
    const float* __restrict__ A_imag,
    float* __restrict__ out)
{
    __shared__ __align__(8) float s_wr[kN2];
    __shared__ __align__(8) float s_wi[kN2];
    __shared__ __align__(8) float s_nwi[kN2];
    __shared__ float s_ctr[kN2];
    __shared__ float s_cti[kN2];
    __shared__ float s_dre[kN2];
    __shared__ float s_dim[kN2];

    const int h   = blockIdx.x;
    const int tid = threadIdx.x;

    if (tid < kN2) {
        const int n = tid;
        float dt  = __expf(log_dt[h]);
        float Are = -__expf(log_A_real[h * kN2 + n]);
        float Aim = A_imag[h * kN2 + n];
        float dre = Are * dt;
        float dim = Aim * dt;
        float er  = __expf(dre);
        float sn, cs;
        __sincosf(dim, &sn, &cs);
        float wr = er * cs, wi = er * sn;
        // (z - 1)
        float e1r = wr - 1.0f, e1i = wi;
        float cr = C_real[h * kN2 + n], ci = C_imag[h * kN2 + n];
        // num = C * (z-1)
        float nr = cr * e1r - ci * e1i;
        float ni = cr * e1i + ci * e1r;
        // Ct = num * conj(A) / |A|^2
        float a2   = Are * Are + Aim * Aim;
        float inva = 1.0f / a2;
        s_ctr[n] = (nr * Are + ni * Aim) * inva;
        s_cti[n] = (ni * Are - nr * Aim) * inva;
        s_wr[n]  = wr;
        s_wi[n]  = wi;
        s_nwi[n] = -wi;
        s_dre[n] = dre;
        s_dim[n] = dim;
    }
    __syncthreads();

    const int   l0  = tid * kChunk;
    const float l0f = (float)l0;

    u64 acc[kChunk];
    #pragma unroll
    for (int j = 0; j < kChunk; j++) acc[j] = 0ULL;  // packed {0.0f, 0.0f}

    const u64* wr_p  = (const u64*)s_wr;
    const u64* wi_p  = (const u64*)s_wi;
    const u64* nwi_p = (const u64*)s_nwi;

    #pragma unroll 1
    for (int p = 0; p < kPairs; p++) {
        const int n0 = 2 * p, n1 = 2 * p + 1;

        float qr0, qi0, qr1, qi1;
        chunk_start(s_dre[n0], s_dim[n0], s_ctr[n0], s_cti[n0], l0f, l0, qr0, qi0);
        chunk_start(s_dre[n1], s_dim[n1], s_ctr[n1], s_cti[n1], l0f, l0, qr1, qi1);

        u64 qr  = pk2(qr0, qr1);
        u64 qi  = pk2(qi0, qi1);
        u64 wr  = wr_p[p];    // broadcast LDS.64, conflict-free
        u64 wi  = wi_p[p];
        u64 nwi = nwi_p[p];

        #pragma unroll
        for (int j = 0; j < kChunk; j++) {
            acc[j] = add2(acc[j], qr);
            u64 t = mul2(qr, wr);
            u64 u = mul2(qr, wi);
            qr = fma2(qi, nwi, t);   // re: qr*wr - qi*wi
            qi = fma2(qi, wr,  u);   // im: qr*wi + qi*wr
        }
    }

    // Reduce packed halves, scale by 2, store as float4 (64B per thread, aligned).
    float4* outv = (float4*)(out + (size_t)h * kL + l0);
    #pragma unroll
    for (int v = 0; v < kChunk / 4; v++) {
        float a0, a1, b0, b1, c0, c1, d0, d1;
        upk2(acc[4 * v + 0], a0, a1);
        upk2(acc[4 * v + 1], b0, b1);
        upk2(acc[4 * v + 2], c0, c1);
        upk2(acc[4 * v + 3], d0, d1);
        float4 o;
        o.x = 2.0f * (a0 + a1);
        o.y = 2.0f * (b0 + b1);
        o.z = 2.0f * (c0 + c1);
        o.w = 2.0f * (d0 + d1);
        outv[v] = o;
    }
}

extern "C" void kernel_launch(void* const* d_in, const int* in_sizes, int n_in,
                              void* d_out, int out_size) {
    const float* log_dt     = (const float*)d_in[0];
    const float* C_real     = (const float*)d_in[1];
    const float* C_imag     = (const float*)d_in[2];
    const float* log_A_real = (const float*)d_in[3];
    const float* A_imag     = (const float*)d_in[4];
    float* out = (float*)d_out;

    s4d_kernel<<<kH, kTPB>>>(log_dt, C_real, C_imag, log_A_real, A_imag, out);
}

// round 3
// speedup vs baseline: 3.3056x; 3.3056x over previous
#include <cuda_runtime.h>
#include <cuda_bf16.h>

// S4D kernel: K[h,l] = 2*Re( sum_n Ct[h,n] * exp(dtA[h,n]*l) )
// R2 change: chunk-start phase reduction is now pure fp32 (exact-product FMA
// residual + 2-term Cody-Waite), eliminating all FP64 (was ~65us of the 103us).

static constexpr int kH     = 1024;
static constexpr int kN2    = 32;
static constexpr int kL     = 4096;
static constexpr int kChunk = 16;
static constexpr int kTPB   = 256;           // kTPB * kChunk == kL
static constexpr int kPairs = kN2 / 2;

typedef unsigned long long u64;

__device__ __forceinline__ u64 pk2(float lo, float hi) {
    u64 r; asm("mov.b64 %0, {%1, %2};" : "=l"(r) : "f"(lo), "f"(hi)); return r;
}
__device__ __forceinline__ void upk2(u64 v, float& lo, float& hi) {
    asm("mov.b64 {%0, %1}, %2;" : "=f"(lo), "=f"(hi) : "l"(v));
}
__device__ __forceinline__ u64 fma2(u64 a, u64 b, u64 c) {
    u64 r; asm("fma.rn.f32x2 %0, %1, %2, %3;" : "=l"(r) : "l"(a), "l"(b), "l"(c)); return r;
}
__device__ __forceinline__ u64 mul2(u64 a, u64 b) {
    u64 r; asm("mul.rn.f32x2 %0, %1, %2;" : "=l"(r) : "l"(a), "l"(b)); return r;
}
__device__ __forceinline__ u64 add2(u64 a, u64 b) {
    u64 r; asm("add.rn.f32x2 %0, %1, %2;" : "=l"(r) : "l"(a), "l"(b)); return r;
}

// q = Ct * z^{l0} for one mode, pure fp32.
// Exact product: p + e == dim*l0 exactly (dim 24-bit mantissa, l0 <= 12 bits).
// Cody-Waite: 2*pi = PI2_HI + PI2_MID; k <= ~6300 so k*PI2_MID (~1e-3) matters.
__device__ __forceinline__ void chunk_start(float dre, float dimv, float ctr, float cti,
                                            float l0f, float& qr, float& qi) {
    const float INV2PI  = 0.15915494309189535f;
    const float PI2_HI  = 6.28318548202514648f;   // fp32(2*pi)
    const float PI2_MID = -1.74845600e-7f;        // 2*pi - PI2_HI
    float mag = __expf(dre * l0f);
    float p   = dimv * l0f;
    float e   = fmaf(dimv, l0f, -p);              // exact residual
    float k   = rintf(p * INV2PI);
    float r   = fmaf(-k, PI2_HI, p);              // exact-ish cancellation via FMA
    r         = r + fmaf(-k, PI2_MID, e);
    float s, c;
    __sincosf(r, &s, &c);
    float pr = mag * c, pi = mag * s;
    qr = ctr * pr - cti * pi;
    qi = ctr * pi + cti * pr;
}

__global__ __launch_bounds__(kTPB) void s4d_kernel(
    const float* __restrict__ log_dt,
    const float* __restrict__ C_real,
    const float* __restrict__ C_imag,
    const float* __restrict__ log_A_real,
    const float* __restrict__ A_imag,
    float* __restrict__ out)
{
    __shared__ __align__(8) float s_wr[kN2];
    __shared__ __align__(8) float s_wi[kN2];
    __shared__ __align__(8) float s_nwi[kN2];
    __shared__ float s_ctr[kN2];
    __shared__ float s_cti[kN2];
    __shared__ float s_dre[kN2];
    __shared__ float s_dim[kN2];

    const int h   = blockIdx.x;
    const int tid = threadIdx.x;

    if (tid < kN2) {
        const int n = tid;
        float dt  = __expf(log_dt[h]);
        float Are = -__expf(log_A_real[h * kN2 + n]);
        float Aim = A_imag[h * kN2 + n];
        float dre = Are * dt;
        float dim = Aim * dt;
        float er  = __expf(dre);
        float sn, cs;
        __sincosf(dim, &sn, &cs);
        float wr = er * cs, wi = er * sn;
        // (z - 1)
        float e1r = wr - 1.0f, e1i = wi;
        float cr = C_real[h * kN2 + n], ci = C_imag[h * kN2 + n];
        // num = C * (z-1)
        float nr = cr * e1r - ci * e1i;
        float ni = cr * e1i + ci * e1r;
        // Ct = num * conj(A) / |A|^2
        float a2   = Are * Are + Aim * Aim;
        float inva = 1.0f / a2;
        s_ctr[n] = (nr * Are + ni * Aim) * inva;
        s_cti[n] = (ni * Are - nr * Aim) * inva;
        s_wr[n]  = wr;
        s_wi[n]  = wi;
        s_nwi[n] = -wi;
        s_dre[n] = dre;
        s_dim[n] = dim;
    }
    __syncthreads();

    const int   l0  = tid * kChunk;
    const float l0f = (float)l0;

    u64 acc[kChunk];
    #pragma unroll
    for (int j = 0; j < kChunk; j++) acc[j] = 0ULL;  // packed {0.0f, 0.0f}

    const u64* wr_p  = (const u64*)s_wr;
    const u64* wi_p  = (const u64*)s_wi;
    const u64* nwi_p = (const u64*)s_nwi;

    #pragma unroll 1
    for (int p = 0; p < kPairs; p++) {
        const int n0 = 2 * p, n1 = 2 * p + 1;

        float qr0, qi0, qr1, qi1;
        chunk_start(s_dre[n0], s_dim[n0], s_ctr[n0], s_cti[n0], l0f, qr0, qi0);
        chunk_start(s_dre[n1], s_dim[n1], s_ctr[n1], s_cti[n1], l0f, qr1, qi1);

        u64 qr  = pk2(qr0, qr1);
        u64 qi  = pk2(qi0, qi1);
        u64 wr  = wr_p[p];    // broadcast LDS.64, conflict-free
        u64 wi  = wi_p[p];
        u64 nwi = nwi_p[p];

        #pragma unroll
        for (int j = 0; j < kChunk; j++) {
            acc[j] = add2(acc[j], qr);
            u64 t = mul2(qr, wr);
            u64 u = mul2(qr, wi);
            qr = fma2(qi, nwi, t);   // re: qr*wr - qi*wi
            qi = fma2(qi, wr,  u);   // im: qr*wi + qi*wr
        }
    }

    // Reduce packed halves, scale by 2, store as float4 (64B per thread, aligned).
    float4* outv = (float4*)(out + (size_t)h * kL + l0);
    #pragma unroll
    for (int v = 0; v < kChunk / 4; v++) {
        float a0, a1, b0, b1, c0, c1, d0, d1;
        upk2(acc[4 * v + 0], a0, a1);
        upk2(acc[4 * v + 1], b0, b1);
        upk2(acc[4 * v + 2], c0, c1);
        upk2(acc[4 * v + 3], d0, d1);
        float4 o;
        o.x = 2.0f * (a0 + a1);
        o.y = 2.0f * (b0 + b1);
        o.z = 2.0f * (c0 + c1);
        o.w = 2.0f * (d0 + d1);
        outv[v] = o;
    }
}

extern "C" void kernel_launch(void* const* d_in, const int* in_sizes, int n_in,
                              void* d_out, int out_size) {
    const float* log_dt     = (const float*)d_in[0];
    const float* C_real     = (const float*)d_in[1];
    const float* C_imag     = (const float*)d_in[2];
    const float* log_A_real = (const float*)d_in[3];
    const float* A_imag     = (const float*)d_in[4];
    float* out = (float*)d_out;

    s4d_kernel<<<kH, kTPB>>>(log_dt, C_real, C_imag, log_A_real, A_imag, out);
}

// round 4
// speedup vs baseline: 3.7564x; 1.1364x over previous
#include <cuda_runtime.h>
#include <cuda_bf16.h>

// S4D kernel: K[h,l] = 2*Re( sum_n Ct[h,n] * exp(dtA[h,n]*l) )
// R4 change: replace the complex geometric recurrence (5 packed f32x2 ops per
// step) with the real 2nd-order recurrence for u = Re(Ct z^l):
//   u_{j+1} = a*u_j - b*u_{j-1},  a = 2 Re(z), b = |z|^2
// -> 3 packed ops per step (mul + fma + add), 40% less FMA-pipe work.
// The factor 2 is folded into Ct at setup.

static constexpr int kH     = 1024;
static constexpr int kN2    = 32;
static constexpr int kL     = 4096;
static constexpr int kChunk = 16;
static constexpr int kTPB   = 256;           // kTPB * kChunk == kL
static constexpr int kPairs = kN2 / 2;

typedef unsigned long long u64;

__device__ __forceinline__ u64 pk2(float lo, float hi) {
    u64 r; asm("mov.b64 %0, {%1, %2};" : "=l"(r) : "f"(lo), "f"(hi)); return r;
}
__device__ __forceinline__ void upk2(u64 v, float& lo, float& hi) {
    asm("mov.b64 {%0, %1}, %2;" : "=f"(lo), "=f"(hi) : "l"(v));
}
__device__ __forceinline__ u64 fma2(u64 a, u64 b, u64 c) {
    u64 r; asm("fma.rn.f32x2 %0, %1, %2, %3;" : "=l"(r) : "l"(a), "l"(b), "l"(c)); return r;
}
__device__ __forceinline__ u64 mul2(u64 a, u64 b) {
    u64 r; asm("mul.rn.f32x2 %0, %1, %2;" : "=l"(r) : "l"(a), "l"(b)); return r;
}
__device__ __forceinline__ u64 add2(u64 a, u64 b) {
    u64 r; asm("add.rn.f32x2 %0, %1, %2;" : "=l"(r) : "l"(a), "l"(b)); return r;
}

// q = Ct * z^{l0} for one mode, pure fp32.
// Exact product: p + e == dim*l0 (dim 24-bit mantissa, l0 <= 12 bits).
// Cody-Waite: 2*pi = PI2_HI + PI2_MID; k <= ~6300 so k*PI2_MID (~1e-3) matters.
__device__ __forceinline__ void chunk_start(float dre, float dimv, float ctr, float cti,
                                            float l0f, float& qr, float& qi) {
    const float INV2PI  = 0.15915494309189535f;
    const float PI2_HI  = 6.28318548202514648f;   // fp32(2*pi)
    const float PI2_MID = -1.74845600e-7f;        // 2*pi - PI2_HI
    float mag = __expf(dre * l0f);
    float p   = dimv * l0f;
    float e   = fmaf(dimv, l0f, -p);              // exact residual
    float k   = rintf(p * INV2PI);
    float r   = fmaf(-k, PI2_HI, p);
    r         = r + fmaf(-k, PI2_MID, e);
    float s, c;
    __sincosf(r, &s, &c);
    float pr = mag * c, pi = mag * s;
    qr = ctr * pr - cti * pi;
    qi = ctr * pi + cti * pr;
}

__global__ __launch_bounds__(kTPB) void s4d_kernel(
    const float* __restrict__ log_dt,
    const float* __restrict__ C_real,
    const float* __restrict__ C_imag,
    const float* __restrict__ log_A_real,
    const float* __restrict__ A_imag,
    float* __restrict__ out)
{
    __shared__ __align__(8) float s_a[kN2];    // 2*Re(z)
    __shared__ __align__(8) float s_nb[kN2];   // -|z|^2
    __shared__ float s_wr[kN2];
    __shared__ float s_wi[kN2];
    __shared__ float s_ctr[kN2];               // 2*Ct (factor 2 folded in)
    __shared__ float s_cti[kN2];
    __shared__ float s_dre[kN2];
    __shared__ float s_dim[kN2];

    const int h   = blockIdx.x;
    const int tid = threadIdx.x;

    if (tid < kN2) {
        const int n = tid;
        float dt  = __expf(log_dt[h]);
        float Are = -__expf(log_A_real[h * kN2 + n]);
        float Aim = A_imag[h * kN2 + n];
        float dre = Are * dt;
        float dim = Aim * dt;
        float er  = __expf(dre);
        float sn, cs;
        __sincosf(dim, &sn, &cs);
        float wr = er * cs, wi = er * sn;
        // (z - 1)
        float e1r = wr - 1.0f, e1i = wi;
        float cr = C_real[h * kN2 + n], ci = C_imag[h * kN2 + n];
        // num = C * (z-1)
        float nr = cr * e1r - ci * e1i;
        float ni = cr * e1i + ci * e1r;
        // Ct = num * conj(A) / |A|^2 ; fold the output factor 2 in here
        float a2   = Are * Are + Aim * Aim;
        float inva = 2.0f / a2;
        s_ctr[n] = (nr * Are + ni * Aim) * inva;
        s_cti[n] = (ni * Are - nr * Aim) * inva;
        s_wr[n]  = wr;
        s_wi[n]  = wi;
        s_a[n]   = 2.0f * wr;
        s_nb[n]  = -(er * er);
        s_dre[n] = dre;
        s_dim[n] = dim;
    }
    __syncthreads();

    const int   l0  = tid * kChunk;
    const float l0f = (float)l0;

    u64 acc[kChunk];
    #pragma unroll
    for (int j = 0; j < kChunk; j++) acc[j] = 0ULL;  // packed {0.0f, 0.0f}

    const u64* a_p  = (const u64*)s_a;
    const u64* nb_p = (const u64*)s_nb;

    #pragma unroll 1
    for (int p = 0; p < kPairs; p++) {
        const int n0 = 2 * p, n1 = 2 * p + 1;

        float qr0, qi0, qr1, qi1;
        chunk_start(s_dre[n0], s_dim[n0], s_ctr[n0], s_cti[n0], l0f, qr0, qi0);
        chunk_start(s_dre[n1], s_dim[n1], s_ctr[n1], s_cti[n1], l0f, qr1, qi1);

        // u1 = Re(q * z) = qr*wr - qi*wi  (2 scalar ops per mode)
        float u1_0 = fmaf(qr0, s_wr[n0], -(qi0 * s_wi[n0]));
        float u1_1 = fmaf(qr1, s_wr[n1], -(qi1 * s_wi[n1]));

        u64 u0 = pk2(qr0, qr1);
        u64 u1 = pk2(u1_0, u1_1);
        u64 a  = a_p[p];    // broadcast LDS.64, conflict-free
        u64 nb = nb_p[p];

        acc[0] = add2(acc[0], u0);
        acc[1] = add2(acc[1], u1);

        #pragma unroll
        for (int j = 2; j < kChunk; j++) {
            u64 t  = mul2(u0, nb);
            u64 un = fma2(u1, a, t);   // u_{j} = a*u_{j-1} - b*u_{j-2}
            acc[j] = add2(acc[j], un);
            u0 = u1; u1 = un;
        }
    }

    // Reduce packed halves, store as float4 (64B per thread, aligned).
    float4* outv = (float4*)(out + (size_t)h * kL + l0);
    #pragma unroll
    for (int v = 0; v < kChunk / 4; v++) {
        float a0, a1, b0, b1, c0, c1, d0, d1;
        upk2(acc[4 * v + 0], a0, a1);
        upk2(acc[4 * v + 1], b0, b1);
        upk2(acc[4 * v + 2], c0, c1);
        upk2(acc[4 * v + 3], d0, d1);
        float4 o;
        o.x = a0 + a1;
        o.y = b0 + b1;
        o.z = c0 + c1;
        o.w = d0 + d1;
        outv[v] = o;
    }
}

extern "C" void kernel_launch(void* const* d_in, const int* in_sizes, int n_in,
                              void* d_out, int out_size) {
    const float* log_dt     = (const float*)d_in[0];
    const float* C_real     = (const float*)d_in[1];
    const float* C_imag     = (const float*)d_in[2];
    const float* log_A_real = (const float*)d_in[3];
    const float* A_imag     = (const float*)d_in[4];
    float* out = (float*)d_out;

    s4d_kernel<<<kH, kTPB>>>(log_dt, C_real, C_imag, log_A_real, A_imag, out);
}

// round 7
// speedup vs baseline: 4.0694x; 1.0833x over previous
#include <cuda_runtime.h>
#include <cuda_bf16.h>

// S4D kernel: K[h,l] = 2*Re( sum_n Ct[h,n] * exp(dtA[h,n]*l) )
// R5 changes:
//  - software-pipeline chunk_start: pair p+1's transcendental chain is computed
//    while pair p's 14-step recurrence runs (hides ~80cyc MUFU latency)
//  - chunk_start fully vectorized in f32x2; rintf replaced by fma-magic-number
//    rounding (no FRND); negations via integer sign-xor (ALU pipe)
//  - per-pair smem params packed into 4x LDS.128 instead of 8x LDS.64

static constexpr int kH     = 1024;
static constexpr int kN2    = 32;
static constexpr int kL     = 4096;
static constexpr int kChunk = 16;
static constexpr int kTPB   = 256;           // kTPB * kChunk == kL
static constexpr int kPairs = kN2 / 2;

typedef unsigned long long u64;

__device__ __forceinline__ u64 pk2(float lo, float hi) {
    u64 r; asm("mov.b64 %0, {%1, %2};" : "=l"(r) : "f"(lo), "f"(hi)); return r;
}
__device__ __forceinline__ void upk2(u64 v, float& lo, float& hi) {
    asm("mov.b64 {%0, %1}, %2;" : "=f"(lo), "=f"(hi) : "l"(v));
}
__device__ __forceinline__ u64 fma2(u64 a, u64 b, u64 c) {
    u64 r; asm("fma.rn.f32x2 %0, %1, %2, %3;" : "=l"(r) : "l"(a), "l"(b), "l"(c)); return r;
}
__device__ __forceinline__ u64 mul2(u64 a, u64 b) {
    u64 r; asm("mul.rn.f32x2 %0, %1, %2;" : "=l"(r) : "l"(a), "l"(b)); return r;
}
__device__ __forceinline__ u64 add2(u64 a, u64 b) {
    u64 r; asm("add.rn.f32x2 %0, %1, %2;" : "=l"(r) : "l"(a), "l"(b)); return r;
}
__device__ __forceinline__ float ex2a(float x) {
    float r; asm("ex2.approx.f32 %0, %1;" : "=f"(r) : "f"(x)); return r;
}
__device__ __forceinline__ float sina(float x) {
    float r; asm("sin.approx.f32 %0, %1;" : "=f"(r) : "f"(x)); return r;
}
__device__ __forceinline__ float cosa(float x) {
    float r; asm("cos.approx.f32 %0, %1;" : "=f"(r) : "f"(x)); return r;
}

static __device__ __forceinline__ u64 SGN2() { return 0x8000000080000000ULL; }

// Packed chunk start for a mode pair: u0 = Re(Ct z^{l0}), u1 = Re(Ct z^{l0+1}),
// both lanes of the f32x2 carry the two modes. Pure fp32:
// exact product (FMA residual) + 2-term Cody-Waite; rint via magic constant.
__device__ __forceinline__ void pair_start(
    float4 g1, float4 g2, float4 g3,
    u64 l0f2, u64 nINV2PI2, u64 MAGIC2, u64 nMAGIC2, u64 PI2HI2, u64 PI2MID2,
    u64& u0pk, u64& u1pk)
{
    u64 dreL2 = pk2(g1.x, g1.y);          // dre * log2(e), per mode
    u64 dim2  = pk2(g1.z, g1.w);
    u64 m2 = mul2(dreL2, l0f2);
    float m0, m1; upk2(m2, m0, m1);
    float mag0 = ex2a(m0), mag1 = ex2a(m1);

    u64 p2   = mul2(dim2, l0f2);
    u64 e2   = fma2(dim2, l0f2, p2 ^ SGN2());     // exact residual of dim*l0
    u64 nk2  = fma2(p2, nINV2PI2, MAGIC2);        // MAGIC - p/2pi (rounded on int grid)
    u64 nkf2 = add2(nk2, nMAGIC2);                // = -rint(p/2pi)
    u64 r2   = fma2(nkf2, PI2HI2, p2);
    r2       = add2(r2, fma2(nkf2, PI2MID2, e2));
    float r0, r1; upk2(r2, r0, r1);
    float s0 = sina(r0), c0 = cosa(r0);
    float s1 = sina(r1), c1 = cosa(r1);

    u64 mag2 = pk2(mag0, mag1);
    u64 pr2  = mul2(mag2, pk2(c0, c1));
    u64 pi2  = mul2(mag2, pk2(s0, s1));
    u64 ctr2 = pk2(g2.x, g2.y);
    u64 cti2 = pk2(g2.z, g2.w);
    u64 qr2  = fma2(cti2, pi2 ^ SGN2(), mul2(ctr2, pr2));   // ctr*pr - cti*pi
    u64 qi2  = fma2(cti2, pr2,          mul2(ctr2, pi2));   // ctr*pi + cti*pr
    u64 wr2  = pk2(g3.x, g3.y);
    u64 nwi2 = pk2(g3.z, g3.w);
    u0pk = qr2;
    u1pk = fma2(qi2, nwi2, mul2(qr2, wr2));                  // Re(q*z)
}

struct ModeParams {
    float dreL2, dim, ctr, cti, wr, nwi, a, nb;
};

__device__ __forceinline__ ModeParams mode_setup(float dt, float lAr, float Aim,
                                                 float cr, float ci) {
    const float LOG2E = 1.44269504088896341f;
    ModeParams mp;
    float Are = -__expf(lAr);
    float dre = Are * dt;
    float dim = Aim * dt;
    float er  = __expf(dre);
    float sn, cs;
    __sincosf(dim, &sn, &cs);
    float wr = er * cs, wi = er * sn;
    float e1r = wr - 1.0f, e1i = wi;
    float nr = cr * e1r - ci * e1i;
    float ni = cr * e1i + ci * e1r;
    float a2   = Are * Are + Aim * Aim;
    float inva = 2.0f / a2;                  // factor 2 of output folded in
    mp.ctr   = (nr * Are + ni * Aim) * inva;
    mp.cti   = (ni * Are - nr * Aim) * inva;
    mp.dreL2 = dre * LOG2E;
    mp.dim   = dim;
    mp.wr    = wr;
    mp.nwi   = -wi;
    mp.a     = 2.0f * wr;
    mp.nb    = -(er * er);
    return mp;
}

__global__ __launch_bounds__(kTPB) void s4d_kernel(
    const float* __restrict__ log_dt,
    const float* __restrict__ C_real,
    const float* __restrict__ C_imag,
    const float* __restrict__ log_A_real,
    const float* __restrict__ A_imag,
    float* __restrict__ out)
{
    __shared__ float4 s_g1[kPairs];   // {dreL2_0, dreL2_1, dim_0, dim_1}
    __shared__ float4 s_g2[kPairs];   // {ctr_0,  ctr_1,  cti_0, cti_1}
    __shared__ float4 s_g3[kPairs];   // {wr_0,   wr_1,   nwi_0, nwi_1}
    __shared__ float4 s_g4[kPairs];   // {a_0,    a_1,    nb_0,  nb_1}

    const int h   = blockIdx.x;
    const int tid = threadIdx.x;

    if (tid < kPairs) {
        const int p = tid, n0 = 2 * p, n1 = n0 + 1;
        float dt = __expf(log_dt[h]);
        ModeParams m0 = mode_setup(dt, log_A_real[h * kN2 + n0], A_imag[h * kN2 + n0],
                                   C_real[h * kN2 + n0], C_imag[h * kN2 + n0]);
        ModeParams m1 = mode_setup(dt, log_A_real[h * kN2 + n1], A_imag[h * kN2 + n1],
                                   C_real[h * kN2 + n1], C_imag[h * kN2 + n1]);
        s_g1[p] = make_float4(m0.dreL2, m1.dreL2, m0.dim, m1.dim);
        s_g2[p] = make_float4(m0.ctr,   m1.ctr,   m0.cti, m1.cti);
        s_g3[p] = make_float4(m0.wr,    m1.wr,    m0.nwi, m1.nwi);
        s_g4[p] = make_float4(m0.a,     m1.a,     m0.nb,  m1.nb);
    }
    __syncthreads();

    const float l0f = (float)(tid * kChunk);
    const u64 l0f2 = pk2(l0f, l0f);

    const float INV2PI  = 0.15915494309189535f;
    const float PI2HI   = 6.28318548202514648f;   // fp32(2*pi)
    const float PI2MID  = -1.74845600e-7f;        // 2*pi - PI2HI
    const float MAGIC   = 12582912.0f;            // 1.5 * 2^23
    const u64 nINV2PI2 = pk2(-INV2PI, -INV2PI);
    const u64 MAGIC2   = pk2(MAGIC, MAGIC);
    const u64 nMAGIC2  = pk2(-MAGIC, -MAGIC);
    const u64 PI2HI2   = pk2(PI2HI, PI2HI);
    const u64 PI2MID2  = pk2(PI2MID, PI2MID);

    u64 acc[kChunk];
    #pragma unroll
    for (int j = 0; j < kChunk; j++) acc[j] = 0ULL;   // packed {0.0f, 0.0f}

    // Prime the pipeline with pair 0's start.
    u64 u0n, u1n;
    pair_start(s_g1[0], s_g2[0], s_g3[0],
               l0f2, nINV2PI2, MAGIC2, nMAGIC2, PI2HI2, PI2MID2, u0n, u1n);

    #pragma unroll 1
    for (int p = 0; p < kPairs; p++) {
        float4 g4 = s_g4[p];
        u64 a  = pk2(g4.x, g4.y);
        u64 nb = pk2(g4.z, g4.w);
        u64 u0 = u0n;
        u64 u1 = u1n;

        // Start of NEXT pair — independent of this pair's recurrence; the
        // scheduler hides its MUFU chain under the fma loop below.
        const int pn = (p + 1) & (kPairs - 1);   // wraps to 0 on last iter (result unused)
        pair_start(s_g1[pn], s_g2[pn], s_g3[pn],
                   l0f2, nINV2PI2, MAGIC2, nMAGIC2, PI2HI2, PI2MID2, u0n, u1n);

        acc[0] = add2(acc[0], u0);
        acc[1] = add2(acc[1], u1);

        #pragma unroll
        for (int j = 2; j < kChunk; j++) {
            u64 t  = mul2(u0, nb);
            u64 un = fma2(u1, a, t);     // u_j = a*u_{j-1} - b*u_{j-2}
            acc[j] = add2(acc[j], un);
            u0 = u1; u1 = un;
        }
    }

    // Reduce packed halves, store as float4 (64B per thread, aligned).
    float4* outv = (float4*)(out + (size_t)h * kL + (size_t)tid * kChunk);
    #pragma unroll
    for (int v = 0; v < kChunk / 4; v++) {
        float a0, a1, b0, b1, c0, c1, d0, d1;
        upk2(acc[4 * v + 0], a0, a1);
        upk2(acc[4 * v + 1], b0, b1);
        upk2(acc[4 * v + 2], c0, c1);
        upk2(acc[4 * v + 3], d0, d1);
        float4 o;
        o.x = a0 + a1;
        o.y = b0 + b1;
        o.z = c0 + c1;
        o.w = d0 + d1;
        outv[v] = o;
    }
}

extern "C" void kernel_launch(void* const* d_in, const int* in_sizes, int n_in,
                              void* d_out, int out_size) {
    const float* log_dt     = (const float*)d_in[0];
    const float* C_real     = (const float*)d_in[1];
    const float* C_imag     = (const float*)d_in[2];
    const float* log_A_real = (const float*)d_in[3];
    const float* A_imag     = (const float*)d_in[4];
    float* out = (float*)d_out;

    s4d_kernel<<<kH, kTPB>>>(log_dt, C_real, C_imag, log_A_real, A_imag, out);
}

// round 8
// speedup vs baseline: 4.1162x; 1.0115x over previous
#include <cuda_runtime.h>
#include <cuda_bf16.h>

// S4D kernel: K[h,l] = 2*Re( sum_n Ct[h,n] * exp(dtA[h,n]*l) )
// R8 change: de-convoy warps. All warps previously executed pairs 0..15 in the
// same order from the same barrier -> lockstep phases (MUFU bursts of all 8
// warps collide, then fma bursts collide; pipes alternate instead of overlap).
// Warp w now processes pairs in rotated order (p + 2w) & 15, so starts and
// recurrence loops of different warps interleave across pipes.

static constexpr int kH     = 1024;
static constexpr int kN2    = 32;
static constexpr int kL     = 4096;
static constexpr int kChunk = 16;
static constexpr int kTPB   = 256;           // kTPB * kChunk == kL
static constexpr int kPairs = kN2 / 2;

typedef unsigned long long u64;

__device__ __forceinline__ u64 pk2(float lo, float hi) {
    u64 r; asm("mov.b64 %0, {%1, %2};" : "=l"(r) : "f"(lo), "f"(hi)); return r;
}
__device__ __forceinline__ void upk2(u64 v, float& lo, float& hi) {
    asm("mov.b64 {%0, %1}, %2;" : "=f"(lo), "=f"(hi) : "l"(v));
}
__device__ __forceinline__ u64 fma2(u64 a, u64 b, u64 c) {
    u64 r; asm("fma.rn.f32x2 %0, %1, %2, %3;" : "=l"(r) : "l"(a), "l"(b), "l"(c)); return r;
}
__device__ __forceinline__ u64 mul2(u64 a, u64 b) {
    u64 r; asm("mul.rn.f32x2 %0, %1, %2;" : "=l"(r) : "l"(a), "l"(b)); return r;
}
__device__ __forceinline__ u64 add2(u64 a, u64 b) {
    u64 r; asm("add.rn.f32x2 %0, %1, %2;" : "=l"(r) : "l"(a), "l"(b)); return r;
}
__device__ __forceinline__ float ex2a(float x) {
    float r; asm("ex2.approx.f32 %0, %1;" : "=f"(r) : "f"(x)); return r;
}
__device__ __forceinline__ float sina(float x) {
    float r; asm("sin.approx.f32 %0, %1;" : "=f"(r) : "f"(x)); return r;
}
__device__ __forceinline__ float cosa(float x) {
    float r; asm("cos.approx.f32 %0, %1;" : "=f"(r) : "f"(x)); return r;
}

static __device__ __forceinline__ u64 SGN2() { return 0x8000000080000000ULL; }

// Packed chunk start for a mode pair: u0 = Re(Ct z^{l0}), u1 = Re(Ct z^{l0+1}).
__device__ __forceinline__ void pair_start(
    float4 g1, float4 g2, float4 g3,
    u64 l0f2, u64 nINV2PI2, u64 MAGIC2, u64 nMAGIC2, u64 PI2HI2, u64 PI2MID2,
    u64& u0pk, u64& u1pk)
{
    u64 dreL2 = pk2(g1.x, g1.y);          // dre * log2(e), per mode
    u64 dim2  = pk2(g1.z, g1.w);
    u64 m2 = mul2(dreL2, l0f2);
    float m0, m1; upk2(m2, m0, m1);
    float mag0 = ex2a(m0), mag1 = ex2a(m1);

    u64 p2   = mul2(dim2, l0f2);
    u64 e2   = fma2(dim2, l0f2, p2 ^ SGN2());     // exact residual of dim*l0
    u64 nk2  = fma2(p2, nINV2PI2, MAGIC2);        // MAGIC - p/2pi (rounded on int grid)
    u64 nkf2 = add2(nk2, nMAGIC2);                // = -rint(p/2pi)
    u64 r2   = fma2(nkf2, PI2HI2, p2);
    r2       = add2(r2, fma2(nkf2, PI2MID2, e2));
    float r0, r1; upk2(r2, r0, r1);
    float s0 = sina(r0), c0 = cosa(r0);
    float s1 = sina(r1), c1 = cosa(r1);

    u64 mag2 = pk2(mag0, mag1);
    u64 pr2  = mul2(mag2, pk2(c0, c1));
    u64 pi2  = mul2(mag2, pk2(s0, s1));
    u64 ctr2 = pk2(g2.x, g2.y);
    u64 cti2 = pk2(g2.z, g2.w);
    u64 qr2  = fma2(cti2, pi2 ^ SGN2(), mul2(ctr2, pr2));   // ctr*pr - cti*pi
    u64 qi2  = fma2(cti2, pr2,          mul2(ctr2, pi2));   // ctr*pi + cti*pr
    u64 wr2  = pk2(g3.x, g3.y);
    u64 nwi2 = pk2(g3.z, g3.w);
    u0pk = qr2;
    u1pk = fma2(qi2, nwi2, mul2(qr2, wr2));                  // Re(q*z)
}

struct ModeParams {
    float dreL2, dim, ctr, cti, wr, nwi, a, nb;
};

__device__ __forceinline__ ModeParams mode_setup(float dt, float lAr, float Aim,
                                                 float cr, float ci) {
    const float LOG2E = 1.44269504088896341f;
    ModeParams mp;
    float Are = -__expf(lAr);
    float dre = Are * dt;
    float dim = Aim * dt;
    float er  = __expf(dre);
    float sn, cs;
    __sincosf(dim, &sn, &cs);
    float wr = er * cs, wi = er * sn;
    float e1r = wr - 1.0f, e1i = wi;
    float nr = cr * e1r - ci * e1i;
    float ni = cr * e1i + ci * e1r;
    float a2   = Are * Are + Aim * Aim;
    float inva = 2.0f / a2;                  // factor 2 of output folded in
    mp.ctr   = (nr * Are + ni * Aim) * inva;
    mp.cti   = (ni * Are - nr * Aim) * inva;
    mp.dreL2 = dre * LOG2E;
    mp.dim   = dim;
    mp.wr    = wr;
    mp.nwi   = -wi;
    mp.a     = 2.0f * wr;
    mp.nb    = -(er * er);
    return mp;
}

__global__ __launch_bounds__(kTPB) void s4d_kernel(
    const float* __restrict__ log_dt,
    const float* __restrict__ C_real,
    const float* __restrict__ C_imag,
    const float* __restrict__ log_A_real,
    const float* __restrict__ A_imag,
    float* __restrict__ out)
{
    __shared__ float4 s_g1[kPairs];   // {dreL2_0, dreL2_1, dim_0, dim_1}
    __shared__ float4 s_g2[kPairs];   // {ctr_0,  ctr_1,  cti_0, cti_1}
    __shared__ float4 s_g3[kPairs];   // {wr_0,   wr_1,   nwi_0, nwi_1}
    __shared__ float4 s_g4[kPairs];   // {a_0,    a_1,    nb_0,  nb_1}

    const int h   = blockIdx.x;
    const int tid = threadIdx.x;

    if (tid < kPairs) {
        const int p = tid, n0 = 2 * p, n1 = n0 + 1;
        float dt = __expf(log_dt[h]);
        ModeParams m0 = mode_setup(dt, log_A_real[h * kN2 + n0], A_imag[h * kN2 + n0],
                                   C_real[h * kN2 + n0], C_imag[h * kN2 + n0]);
        ModeParams m1 = mode_setup(dt, log_A_real[h * kN2 + n1], A_imag[h * kN2 + n1],
                                   C_real[h * kN2 + n1], C_imag[h * kN2 + n1]);
        s_g1[p] = make_float4(m0.dreL2, m1.dreL2, m0.dim, m1.dim);
        s_g2[p] = make_float4(m0.ctr,   m1.ctr,   m0.cti, m1.cti);
        s_g3[p] = make_float4(m0.wr,    m1.wr,    m0.nwi, m1.nwi);
        s_g4[p] = make_float4(m0.a,     m1.a,     m0.nb,  m1.nb);
    }
    __syncthreads();

    const float l0f = (float)(tid * kChunk);
    const u64 l0f2 = pk2(l0f, l0f);

    // Per-warp rotation of the pair order: de-synchronizes warp phases.
    const int rot = (tid >> 5) * 2;               // warp_id * 2, warp-uniform

    const float INV2PI  = 0.15915494309189535f;
    const float PI2HI   = 6.28318548202514648f;   // fp32(2*pi)
    const float PI2MID  = -1.74845600e-7f;        // 2*pi - PI2HI
    const float MAGIC   = 12582912.0f;            // 1.5 * 2^23
    const u64 nINV2PI2 = pk2(-INV2PI, -INV2PI);
    const u64 MAGIC2   = pk2(MAGIC, MAGIC);
    const u64 nMAGIC2  = pk2(-MAGIC, -MAGIC);
    const u64 PI2HI2   = pk2(PI2HI, PI2HI);
    const u64 PI2MID2  = pk2(PI2MID, PI2MID);

    u64 acc[kChunk];
    #pragma unroll
    for (int j = 0; j < kChunk; j++) acc[j] = 0ULL;   // packed {0.0f, 0.0f}

    // Prime the pipeline with this warp's first pair.
    u64 u0n, u1n;
    pair_start(s_g1[rot], s_g2[rot], s_g3[rot],
               l0f2, nINV2PI2, MAGIC2, nMAGIC2, PI2HI2, PI2MID2, u0n, u1n);

    #pragma unroll 1
    for (int p = 0; p < kPairs; p++) {
        const int pc = (p + rot) & (kPairs - 1);
        float4 g4 = s_g4[pc];
        u64 a  = pk2(g4.x, g4.y);
        u64 nb = pk2(g4.z, g4.w);
        u64 u0 = u0n;
        u64 u1 = u1n;

        // Start of NEXT pair — independent of this pair's recurrence; the
        // scheduler hides its MUFU chain under the fma loop below.
        const int pn = (p + 1 + rot) & (kPairs - 1);  // wraps on last iter (unused)
        pair_start(s_g1[pn], s_g2[pn], s_g3[pn],
                   l0f2, nINV2PI2, MAGIC2, nMAGIC2, PI2HI2, PI2MID2, u0n, u1n);

        acc[0] = add2(acc[0], u0);
        acc[1] = add2(acc[1], u1);

        #pragma unroll
        for (int j = 2; j < kChunk; j++) {
            u64 t  = mul2(u0, nb);
            u64 un = fma2(u1, a, t);     // u_j = a*u_{j-1} - b*u_{j-2}
            acc[j] = add2(acc[j], un);
            u0 = u1; u1 = un;
        }
    }

    // Reduce packed halves, store as float4 (64B per thread, aligned).
    float4* outv = (float4*)(out + (size_t)h * kL + (size_t)tid * kChunk);
    #pragma unroll
    for (int v = 0; v < kChunk / 4; v++) {
        float a0, a1, b0, b1, c0, c1, d0, d1;
        upk2(acc[4 * v + 0], a0, a1);
        upk2(acc[4 * v + 1], b0, b1);
        upk2(acc[4 * v + 2], c0, c1);
        upk2(acc[4 * v + 3], d0, d1);
        float4 o;
        o.x = a0 + a1;
        o.y = b0 + b1;
        o.z = c0 + c1;
        o.w = d0 + d1;
        outv[v] = o;
    }
}

extern "C" void kernel_launch(void* const* d_in, const int* in_sizes, int n_in,
                              void* d_out, int out_size) {
    const float* log_dt     = (const float*)d_in[0];
    const float* C_real     = (const float*)d_in[1];
    const float* C_imag     = (const float*)d_in[2];
    const float* log_A_real = (const float*)d_in[3];
    const float* A_imag     = (const float*)d_in[4];
    float* out = (float*)d_out;

    s4d_kernel<<<kH, kTPB>>>(log_dt, C_real, C_imag, log_A_real, A_imag, out);
}

// round 9
// speedup vs baseline: 4.4394x; 1.0785x over previous
#include <cuda_runtime.h>
#include <cuda_bf16.h>

// S4D kernel: K[h,l] = 2*Re( sum_n Ct[h,n] * exp(dtA[h,n]*l) )
// R9 change: restructure main loop from outer-pair/inner-l (ONE serial 4-cyc
// FFMA2 chain per warp, issue density ~0.6) to outer-l/inner-pair with 8
// independent recurrence chains live per warp. Two groups of 8 pairs keep
// register pressure ~125. Goal: per-warp ILP -> issue-limited, fma pipe >70%.

static constexpr int kH     = 1024;
static constexpr int kN2    = 32;
static constexpr int kL     = 4096;
static constexpr int kChunk = 16;
static constexpr int kTPB   = 256;           // kTPB * kChunk == kL
static constexpr int kPairs = kN2 / 2;
static constexpr int kGrp   = 8;             // pairs per ILP group

typedef unsigned long long u64;

__device__ __forceinline__ u64 pk2(float lo, float hi) {
    u64 r; asm("mov.b64 %0, {%1, %2};" : "=l"(r) : "f"(lo), "f"(hi)); return r;
}
__device__ __forceinline__ void upk2(u64 v, float& lo, float& hi) {
    asm("mov.b64 {%0, %1}, %2;" : "=f"(lo), "=f"(hi) : "l"(v));
}
__device__ __forceinline__ u64 fma2(u64 a, u64 b, u64 c) {
    u64 r; asm("fma.rn.f32x2 %0, %1, %2, %3;" : "=l"(r) : "l"(a), "l"(b), "l"(c)); return r;
}
__device__ __forceinline__ u64 mul2(u64 a, u64 b) {
    u64 r; asm("mul.rn.f32x2 %0, %1, %2;" : "=l"(r) : "l"(a), "l"(b)); return r;
}
__device__ __forceinline__ u64 add2(u64 a, u64 b) {
    u64 r; asm("add.rn.f32x2 %0, %1, %2;" : "=l"(r) : "l"(a), "l"(b)); return r;
}
__device__ __forceinline__ float ex2a(float x) {
    float r; asm("ex2.approx.f32 %0, %1;" : "=f"(r) : "f"(x)); return r;
}
__device__ __forceinline__ float sina(float x) {
    float r; asm("sin.approx.f32 %0, %1;" : "=f"(r) : "f"(x)); return r;
}
__device__ __forceinline__ float cosa(float x) {
    float r; asm("cos.approx.f32 %0, %1;" : "=f"(r) : "f"(x)); return r;
}

static __device__ __forceinline__ u64 SGN2() { return 0x8000000080000000ULL; }

// Packed chunk start for a mode pair: u0 = Re(Ct z^{l0}), u1 = Re(Ct z^{l0+1}).
__device__ __forceinline__ void pair_start(
    float4 g1, float4 g2, float4 g3,
    u64 l0f2, u64 nINV2PI2, u64 MAGIC2, u64 nMAGIC2, u64 PI2HI2, u64 PI2MID2,
    u64& u0pk, u64& u1pk)
{
    u64 dreL2 = pk2(g1.x, g1.y);          // dre * log2(e), per mode
    u64 dim2  = pk2(g1.z, g1.w);
    u64 m2 = mul2(dreL2, l0f2);
    float m0, m1; upk2(m2, m0, m1);
    float mag0 = ex2a(m0), mag1 = ex2a(m1);

    u64 p2   = mul2(dim2, l0f2);
    u64 e2   = fma2(dim2, l0f2, p2 ^ SGN2());     // exact residual of dim*l0
    u64 nk2  = fma2(p2, nINV2PI2, MAGIC2);        // MAGIC - p/2pi (rounded on int grid)
    u64 nkf2 = add2(nk2, nMAGIC2);                // = -rint(p/2pi)
    u64 r2   = fma2(nkf2, PI2HI2, p2);
    r2       = add2(r2, fma2(nkf2, PI2MID2, e2));
    float r0, r1; upk2(r2, r0, r1);
    float s0 = sina(r0), c0 = cosa(r0);
    float s1 = sina(r1), c1 = cosa(r1);

    u64 mag2 = pk2(mag0, mag1);
    u64 pr2  = mul2(mag2, pk2(c0, c1));
    u64 pi2  = mul2(mag2, pk2(s0, s1));
    u64 ctr2 = pk2(g2.x, g2.y);
    u64 cti2 = pk2(g2.z, g2.w);
    u64 qr2  = fma2(cti2, pi2 ^ SGN2(), mul2(ctr2, pr2));   // ctr*pr - cti*pi
    u64 qi2  = fma2(cti2, pr2,          mul2(ctr2, pi2));   // ctr*pi + cti*pr
    u64 wr2  = pk2(g3.x, g3.y);
    u64 nwi2 = pk2(g3.z, g3.w);
    u0pk = qr2;
    u1pk = fma2(qi2, nwi2, mul2(qr2, wr2));                  // Re(q*z)
}

struct ModeParams {
    float dreL2, dim, ctr, cti, wr, nwi, a, nb;
};

__device__ __forceinline__ ModeParams mode_setup(float dt, float lAr, float Aim,
                                                 float cr, float ci) {
    const float LOG2E = 1.44269504088896341f;
    ModeParams mp;
    float Are = -__expf(lAr);
    float dre = Are * dt;
    float dim = Aim * dt;
    float er  = __expf(dre);
    float sn, cs;
    __sincosf(dim, &sn, &cs);
    float wr = er * cs, wi = er * sn;
    float e1r = wr - 1.0f, e1i = wi;
    float nr = cr * e1r - ci * e1i;
    float ni = cr * e1i + ci * e1r;
    float a2   = Are * Are + Aim * Aim;
    float inva = 2.0f / a2;                  // factor 2 of output folded in
    mp.ctr   = (nr * Are + ni * Aim) * inva;
    mp.cti   = (ni * Are - nr * Aim) * inva;
    mp.dreL2 = dre * LOG2E;
    mp.dim   = dim;
    mp.wr    = wr;
    mp.nwi   = -wi;
    mp.a     = 2.0f * wr;
    mp.nb    = -(er * er);
    return mp;
}

__global__ __launch_bounds__(kTPB) void s4d_kernel(
    const float* __restrict__ log_dt,
    const float* __restrict__ C_real,
    const float* __restrict__ C_imag,
    const float* __restrict__ log_A_real,
    const float* __restrict__ A_imag,
    float* __restrict__ out)
{
    __shared__ float4 s_g1[kPairs];   // {dreL2_0, dreL2_1, dim_0, dim_1}
    __shared__ float4 s_g2[kPairs];   // {ctr_0,  ctr_1,  cti_0, cti_1}
    __shared__ float4 s_g3[kPairs];   // {wr_0,   wr_1,   nwi_0, nwi_1}
    __shared__ float4 s_g4[kPairs];   // {a_0,    a_1,    nb_0,  nb_1}

    const int h   = blockIdx.x;
    const int tid = threadIdx.x;

    if (tid < kPairs) {
        const int p = tid, n0 = 2 * p, n1 = n0 + 1;
        float dt = __expf(log_dt[h]);
        ModeParams m0 = mode_setup(dt, log_A_real[h * kN2 + n0], A_imag[h * kN2 + n0],
                                   C_real[h * kN2 + n0], C_imag[h * kN2 + n0]);
        ModeParams m1 = mode_setup(dt, log_A_real[h * kN2 + n1], A_imag[h * kN2 + n1],
                                   C_real[h * kN2 + n1], C_imag[h * kN2 + n1]);
        s_g1[p] = make_float4(m0.dreL2, m1.dreL2, m0.dim, m1.dim);
        s_g2[p] = make_float4(m0.ctr,   m1.ctr,   m0.cti, m1.cti);
        s_g3[p] = make_float4(m0.wr,    m1.wr,    m0.nwi, m1.nwi);
        s_g4[p] = make_float4(m0.a,     m1.a,     m0.nb,  m1.nb);
    }
    __syncthreads();

    const float l0f = (float)(tid * kChunk);
    const u64 l0f2 = pk2(l0f, l0f);

    const float INV2PI  = 0.15915494309189535f;
    const float PI2HI   = 6.28318548202514648f;   // fp32(2*pi)
    const float PI2MID  = -1.74845600e-7f;        // 2*pi - PI2HI
    const float MAGIC   = 12582912.0f;            // 1.5 * 2^23
    const u64 nINV2PI2 = pk2(-INV2PI, -INV2PI);
    const u64 MAGIC2   = pk2(MAGIC, MAGIC);
    const u64 nMAGIC2  = pk2(-MAGIC, -MAGIC);
    const u64 PI2HI2   = pk2(PI2HI, PI2HI);
    const u64 PI2MID2  = pk2(PI2MID, PI2MID);

    u64 acc[kChunk];
    #pragma unroll
    for (int j = 0; j < kChunk; j++) acc[j] = 0ULL;   // packed {0.0f, 0.0f}

    #pragma unroll 1
    for (int g = 0; g < kPairs / kGrp; g++) {
        u64 A[kGrp], NB[kGrp], U0[kGrp], U1[kGrp];

        // Start 8 independent chains (MUFU bursts overlap via ILP).
        #pragma unroll
        for (int i = 0; i < kGrp; i++) {
            const int p = g * kGrp + i;
            float4 g4 = s_g4[p];
            A[i]  = pk2(g4.x, g4.y);
            NB[i] = pk2(g4.z, g4.w);
            pair_start(s_g1[p], s_g2[p], s_g3[p],
                       l0f2, nINV2PI2, MAGIC2, nMAGIC2, PI2HI2, PI2MID2,
                       U0[i], U1[i]);
        }

        #pragma unroll
        for (int i = 0; i < kGrp; i++) {
            acc[0] = add2(acc[0], U0[i]);
            acc[1] = add2(acc[1], U1[i]);
        }

        // Outer l-step, inner pair: 8 independent FFMA2 chains per step.
        #pragma unroll
        for (int j = 2; j < kChunk; j++) {
            #pragma unroll
            for (int i = 0; i < kGrp; i++) {
                u64 un = fma2(U1[i], A[i], mul2(U0[i], NB[i]));
                acc[j] = add2(acc[j], un);
                U0[i] = U1[i];
                U1[i] = un;
            }
        }
    }

    // Reduce packed halves, store as float4 (64B per thread, aligned).
    float4* outv = (float4*)(out + (size_t)h * kL + (size_t)tid * kChunk);
    #pragma unroll
    for (int v = 0; v < kChunk / 4; v++) {
        float a0, a1, b0, b1, c0, c1, d0, d1;
        upk2(acc[4 * v + 0], a0, a1);
        upk2(acc[4 * v + 1], b0, b1);
        upk2(acc[4 * v + 2], c0, c1);
        upk2(acc[4 * v + 3], d0, d1);
        float4 o;
        o.x = a0 + a1;
        o.y = b0 + b1;
        o.z = c0 + c1;
        o.w = d0 + d1;
        outv[v] = o;
    }
}

extern "C" void kernel_launch(void* const* d_in, const int* in_sizes, int n_in,
                              void* d_out, int out_size) {
    const float* log_dt     = (const float*)d_in[0];
    const float* C_real     = (const float*)d_in[1];
    const float* C_imag     = (const float*)d_in[2];
    const float* log_A_real = (const float*)d_in[3];
    const float* A_imag     = (const float*)d_in[4];
    float* out = (float*)d_out;

    s4d_kernel<<<kH, kTPB>>>(log_dt, C_real, C_imag, log_A_real, A_imag, out);
}

// round 10
// speedup vs baseline: 4.4826x; 1.0097x over previous
#include <cuda_runtime.h>
#include <cuda_bf16.h>

// S4D kernel: K[h,l] = 2*Re( sum_n Ct[h,n] * exp(dtA[h,n]*l) )
// R10 change: break the recurrence's carried mul->fma chain (8 cyc/link) by
// lagging the product:  W_j = (-b)*u_j  computed one step early, so
//   u_{j+1} = fma(a, u_j, W_{j-1})
// leaves a single-FMA2 carried chain (4 cyc/link). W's mul has 8 cyc of slack.
// Same op count, bitwise-identical math; per-warp issue density doubles
// (0.375 -> 0.75), saturating the issue slots regardless of ptxas ordering.

static constexpr int kH     = 1024;
static constexpr int kN2    = 32;
static constexpr int kL     = 4096;
static constexpr int kChunk = 16;
static constexpr int kTPB   = 256;           // kTPB * kChunk == kL
static constexpr int kPairs = kN2 / 2;
static constexpr int kGrp   = 8;             // pairs per ILP group

typedef unsigned long long u64;

__device__ __forceinline__ u64 pk2(float lo, float hi) {
    u64 r; asm("mov.b64 %0, {%1, %2};" : "=l"(r) : "f"(lo), "f"(hi)); return r;
}
__device__ __forceinline__ void upk2(u64 v, float& lo, float& hi) {
    asm("mov.b64 {%0, %1}, %2;" : "=f"(lo), "=f"(hi) : "l"(v));
}
__device__ __forceinline__ u64 fma2(u64 a, u64 b, u64 c) {
    u64 r; asm("fma.rn.f32x2 %0, %1, %2, %3;" : "=l"(r) : "l"(a), "l"(b), "l"(c)); return r;
}
__device__ __forceinline__ u64 mul2(u64 a, u64 b) {
    u64 r; asm("mul.rn.f32x2 %0, %1, %2;" : "=l"(r) : "l"(a), "l"(b)); return r;
}
__device__ __forceinline__ u64 add2(u64 a, u64 b) {
    u64 r; asm("add.rn.f32x2 %0, %1, %2;" : "=l"(r) : "l"(a), "l"(b)); return r;
}
__device__ __forceinline__ float ex2a(float x) {
    float r; asm("ex2.approx.f32 %0, %1;" : "=f"(r) : "f"(x)); return r;
}
__device__ __forceinline__ float sina(float x) {
    float r; asm("sin.approx.f32 %0, %1;" : "=f"(r) : "f"(x)); return r;
}
__device__ __forceinline__ float cosa(float x) {
    float r; asm("cos.approx.f32 %0, %1;" : "=f"(r) : "f"(x)); return r;
}

static __device__ __forceinline__ u64 SGN2() { return 0x8000000080000000ULL; }

// Packed chunk start for a mode pair: u0 = Re(Ct z^{l0}), u1 = Re(Ct z^{l0+1}).
__device__ __forceinline__ void pair_start(
    float4 g1, float4 g2, float4 g3,
    u64 l0f2, u64 nINV2PI2, u64 MAGIC2, u64 nMAGIC2, u64 PI2HI2, u64 PI2MID2,
    u64& u0pk, u64& u1pk)
{
    u64 dreL2 = pk2(g1.x, g1.y);          // dre * log2(e), per mode
    u64 dim2  = pk2(g1.z, g1.w);
    u64 m2 = mul2(dreL2, l0f2);
    float m0, m1; upk2(m2, m0, m1);
    float mag0 = ex2a(m0), mag1 = ex2a(m1);

    u64 p2   = mul2(dim2, l0f2);
    u64 e2   = fma2(dim2, l0f2, p2 ^ SGN2());     // exact residual of dim*l0
    u64 nk2  = fma2(p2, nINV2PI2, MAGIC2);        // MAGIC - p/2pi (rounded on int grid)
    u64 nkf2 = add2(nk2, nMAGIC2);                // = -rint(p/2pi)
    u64 r2   = fma2(nkf2, PI2HI2, p2);
    r2       = add2(r2, fma2(nkf2, PI2MID2, e2));
    float r0, r1; upk2(r2, r0, r1);
    float s0 = sina(r0), c0 = cosa(r0);
    float s1 = sina(r1), c1 = cosa(r1);

    u64 mag2 = pk2(mag0, mag1);
    u64 pr2  = mul2(mag2, pk2(c0, c1));
    u64 pi2  = mul2(mag2, pk2(s0, s1));
    u64 ctr2 = pk2(g2.x, g2.y);
    u64 cti2 = pk2(g2.z, g2.w);
    u64 qr2  = fma2(cti2, pi2 ^ SGN2(), mul2(ctr2, pr2));   // ctr*pr - cti*pi
    u64 qi2  = fma2(cti2, pr2,          mul2(ctr2, pi2));   // ctr*pi + cti*pr
    u64 wr2  = pk2(g3.x, g3.y);
    u64 nwi2 = pk2(g3.z, g3.w);
    u0pk = qr2;
    u1pk = fma2(qi2, nwi2, mul2(qr2, wr2));                  // Re(q*z)
}

struct ModeParams {
    float dreL2, dim, ctr, cti, wr, nwi, a, nb;
};

__device__ __forceinline__ ModeParams mode_setup(float dt, float lAr, float Aim,
                                                 float cr, float ci) {
    const float LOG2E = 1.44269504088896341f;
    ModeParams mp;
    float Are = -__expf(lAr);
    float dre = Are * dt;
    float dim = Aim * dt;
    float er  = __expf(dre);
    float sn, cs;
    __sincosf(dim, &sn, &cs);
    float wr = er * cs, wi = er * sn;
    float e1r = wr - 1.0f, e1i = wi;
    float nr = cr * e1r - ci * e1i;
    float ni = cr * e1i + ci * e1r;
    float a2   = Are * Are + Aim * Aim;
    float inva = 2.0f / a2;                  // factor 2 of output folded in
    mp.ctr   = (nr * Are + ni * Aim) * inva;
    mp.cti   = (ni * Are - nr * Aim) * inva;
    mp.dreL2 = dre * LOG2E;
    mp.dim   = dim;
    mp.wr    = wr;
    mp.nwi   = -wi;
    mp.a     = 2.0f * wr;
    mp.nb    = -(er * er);
    return mp;
}

__global__ __launch_bounds__(kTPB) void s4d_kernel(
    const float* __restrict__ log_dt,
    const float* __restrict__ C_real,
    const float* __restrict__ C_imag,
    const float* __restrict__ log_A_real,
    const float* __restrict__ A_imag,
    float* __restrict__ out)
{
    __shared__ float4 s_g1[kPairs];   // {dreL2_0, dreL2_1, dim_0, dim_1}
    __shared__ float4 s_g2[kPairs];   // {ctr_0,  ctr_1,  cti_0, cti_1}
    __shared__ float4 s_g3[kPairs];   // {wr_0,   wr_1,   nwi_0, nwi_1}
    __shared__ float4 s_g4[kPairs];   // {a_0,    a_1,    nb_0,  nb_1}

    const int h   = blockIdx.x;
    const int tid = threadIdx.x;

    if (tid < kPairs) {
        const int p = tid, n0 = 2 * p, n1 = n0 + 1;
        float dt = __expf(log_dt[h]);
        ModeParams m0 = mode_setup(dt, log_A_real[h * kN2 + n0], A_imag[h * kN2 + n0],
                                   C_real[h * kN2 + n0], C_imag[h * kN2 + n0]);
        ModeParams m1 = mode_setup(dt, log_A_real[h * kN2 + n1], A_imag[h * kN2 + n1],
                                   C_real[h * kN2 + n1], C_imag[h * kN2 + n1]);
        s_g1[p] = make_float4(m0.dreL2, m1.dreL2, m0.dim, m1.dim);
        s_g2[p] = make_float4(m0.ctr,   m1.ctr,   m0.cti, m1.cti);
        s_g3[p] = make_float4(m0.wr,    m1.wr,    m0.nwi, m1.nwi);
        s_g4[p] = make_float4(m0.a,     m1.a,     m0.nb,  m1.nb);
    }
    __syncthreads();

    const float l0f = (float)(tid * kChunk);
    const u64 l0f2 = pk2(l0f, l0f);

    const float INV2PI  = 0.15915494309189535f;
    const float PI2HI   = 6.28318548202514648f;   // fp32(2*pi)
    const float PI2MID  = -1.74845600e-7f;        // 2*pi - PI2HI
    const float MAGIC   = 12582912.0f;            // 1.5 * 2^23
    const u64 nINV2PI2 = pk2(-INV2PI, -INV2PI);
    const u64 MAGIC2   = pk2(MAGIC, MAGIC);
    const u64 nMAGIC2  = pk2(-MAGIC, -MAGIC);
    const u64 PI2HI2   = pk2(PI2HI, PI2HI);
    const u64 PI2MID2  = pk2(PI2MID, PI2MID);

    u64 acc[kChunk];
    #pragma unroll
    for (int j = 0; j < kChunk; j++) acc[j] = 0ULL;   // packed {0.0f, 0.0f}

    #pragma unroll 1
    for (int g = 0; g < kPairs / kGrp; g++) {
        u64 A[kGrp], NB[kGrp], U1[kGrp], W[kGrp];

        // Start kGrp independent chains (MUFU bursts overlap via ILP).
        #pragma unroll
        for (int i = 0; i < kGrp; i++) {
            const int p = g * kGrp + i;
            float4 g4 = s_g4[p];
            A[i]  = pk2(g4.x, g4.y);
            NB[i] = pk2(g4.z, g4.w);
            u64 u0;
            pair_start(s_g1[p], s_g2[p], s_g3[p],
                       l0f2, nINV2PI2, MAGIC2, nMAGIC2, PI2HI2, PI2MID2,
                       u0, U1[i]);
            acc[0] = add2(acc[0], u0);
            acc[1] = add2(acc[1], U1[i]);
            W[i]   = mul2(u0, NB[i]);      // W = (-b)*u_0, lagged product
        }

        // Recurrence: carried chain is ONE fma2 per link (4 cyc); the mul2
        // feeding W has a full link of slack; the acc add is off-chain.
        #pragma unroll
        for (int j = 2; j < kChunk; j++) {
            #pragma unroll
            for (int i = 0; i < kGrp; i++) {
                u64 un = fma2(U1[i], A[i], W[i]);   // u_j = a*u_{j-1} - b*u_{j-2}
                W[i]   = mul2(U1[i], NB[i]);        // (-b)*u_{j-1}, for next link
                acc[j] = add2(acc[j], un);
                U1[i]  = un;
            }
        }
    }

    // Reduce packed halves, store as float4 (64B per thread, aligned).
    float4* outv = (float4*)(out + (size_t)h * kL + (size_t)tid * kChunk);
    #pragma unroll
    for (int v = 0; v < kChunk / 4; v++) {
        float a0, a1, b0, b1, c0, c1, d0, d1;
        upk2(acc[4 * v + 0], a0, a1);
        upk2(acc[4 * v + 1], b0, b1);
        upk2(acc[4 * v + 2], c0, c1);
        upk2(acc[4 * v + 3], d0, d1);
        float4 o;
        o.x = a0 + a1;
        o.y = b0 + b1;
        o.z = c0 + c1;
        o.w = d0 + d1;
        outv[v] = o;
    }
}

extern "C" void kernel_launch(void* const* d_in, const int* in_sizes, int n_in,
                              void* d_out, int out_size) {
    const float* log_dt     = (const float*)d_in[0];
    const float* C_real     = (const float*)d_in[1];
    const float* C_imag     = (const float*)d_in[2];
    const float* log_A_real = (const float*)d_in[3];
    const float* A_imag     = (const float*)d_in[4];
    float* out = (float*)d_out;

    s4d_kernel<<<kH, kTPB>>>(log_dt, C_real, C_imag, log_A_real, A_imag, out);
}